// round 7
// baseline (speedup 1.0000x reference)
#include <cuda_runtime.h>
#include <cuda_bf16.h>
#include <stdint.h>
#include <math.h>

#define HID   256
#define BATCH 16384

// ---- output layout (floats) ----
#define OFF_HNEXT 0
#define OFF_GSTR  (BATCH*HID)
#define OFF_GNODE (OFF_GSTR + 9)
#define OFF_MARG  (OFF_GNODE + (long)BATCH*9*HID)
#define GN_STRIDE (9*HID)

// ---- static device scratch ----
// activations (bf16 hi/lo splits, row-major [BATCH][HID]):
// 0:x 1:h 2:z1 3:r 4:rh 5:h_tilde 6:omz 7:zh_tilde 8:z2h
__device__ __align__(16) __nv_bfloat16 g_act[9][2][(size_t)BATCH*HID];
// weight tiles [n(64)][kk(64)] bf16 (i.e. W^T): [e][mat][sp][nt][ch]
__device__ __align__(16) __nv_bfloat16 g_w[3*2*2*4*4*4096];
#define W_IDX(k,mat,sp,nt,ch) ((((((size_t)(k)*2+(mat))*2+(sp))*4+(nt))*4+(ch))*4096)
// candidates (pre-bias) [row][e 0..2][256] fp32 (also used as MUL-stage stash)
__device__ __align__(16) float g_cand[(size_t)BATCH*3*HID];
__device__ float g_s[24];

// ---- helpers ----
__device__ __forceinline__ uint32_t smem_u32(const void* p) {
    uint32_t a;
    asm("{ .reg .u64 t; cvta.to.shared.u64 t, %1; cvt.u32.u64 %0, t; }" : "=r"(a) : "l"(p));
    return a;
}
__device__ __forceinline__ void cpasync16(uint32_t dst, const void* src) {
    asm volatile("cp.async.cg.shared.global [%0], [%1], 16;" :: "r"(dst), "l"(src));
}
#define CP_COMMIT() asm volatile("cp.async.commit_group;" ::: "memory")
#define CP_WAIT(n)  asm volatile("cp.async.wait_group %0;" :: "n"(n) : "memory")

__device__ __forceinline__ void ldsm4(uint32_t* r, uint32_t addr) {
    asm volatile("ldmatrix.sync.aligned.m8n8.x4.shared.b16 {%0,%1,%2,%3}, [%4];"
        : "=r"(r[0]), "=r"(r[1]), "=r"(r[2]), "=r"(r[3]) : "r"(addr));
}
__device__ __forceinline__ void mma16816(float* c, const uint32_t* a, uint32_t b0, uint32_t b1) {
    asm volatile("mma.sync.aligned.m16n8k16.row.col.f32.bf16.bf16.f32 "
        "{%0,%1,%2,%3}, {%4,%5,%6,%7}, {%8,%9}, {%0,%1,%2,%3};"
        : "+f"(c[0]), "+f"(c[1]), "+f"(c[2]), "+f"(c[3])
        : "r"(a[0]), "r"(a[1]), "r"(a[2]), "r"(a[3]), "r"(b0), "r"(b1));
}
__device__ __forceinline__ void split_bf(float v, __nv_bfloat16& hi, __nv_bfloat16& lo) {
    hi = __float2bfloat16(v);
    lo = __float2bfloat16(v - __bfloat162float(hi));
}
__device__ __forceinline__ uint32_t pack2(__nv_bfloat16 a, __nv_bfloat16 b) {
    __nv_bfloat162 t; t.x = a; t.y = b;
    return *reinterpret_cast<uint32_t*>(&t);
}
// swizzled byte offset within a [rows][64 bf16] tile (128B rows)
__device__ __forceinline__ int swz(int r, int cB) { return (r*128 + cB) ^ ((r & 7) << 4); }

__global__ void zero_s_kernel() { if (threadIdx.x < 24) g_s[threadIdx.x] = 0.0f; }

// split + transpose weights into [n][kk] tiles
__global__ void __launch_bounds__(256) wprep_kernel(const float* __restrict__ L, const float* __restrict__ R) {
    int b = blockIdx.x;
    int ch = b & 3, nt = (b >> 2) & 3, mat = (b >> 4) & 1, k = b >> 5;
    const float* W = (mat ? R : L) + (size_t)k*HID*HID;
    __nv_bfloat16* th = g_w + W_IDX(k, mat, 0, nt, ch);
    __nv_bfloat16* tl = g_w + W_IDX(k, mat, 1, nt, ch);
    for (int e = threadIdx.x; e < 4096; e += 256) {
        int n = e >> 6, kk = e & 63;
        float w = W[(size_t)(ch*64 + kk)*HID + nt*64 + n];
        __nv_bfloat16 hi, lo; split_bf(w, hi, lo);
        th[n*64 + kk] = hi; tl[n*64 + kk] = lo;
    }
}

// split x,h into g_act[0], g_act[1]
__global__ void __launch_bounds__(256) xconv_kernel(const float* __restrict__ x, const float* __restrict__ h) {
    size_t i = (size_t)blockIdx.x*256 + threadIdx.x;
    if (i >= (size_t)BATCH*HID/4) return;
    #pragma unroll
    for (int t = 0; t < 2; t++) {
        const float4 v = reinterpret_cast<const float4*>(t ? h : x)[i];
        __nv_bfloat16 h0,h1,h2,h3,l0,l1,l2,l3;
        split_bf(v.x,h0,l0); split_bf(v.y,h1,l1); split_bf(v.z,h2,l2); split_bf(v.w,h3,l3);
        uint2 uh; uh.x = pack2(h0,h1); uh.y = pack2(h2,h3);
        uint2 ul; ul.x = pack2(l0,l1); ul.y = pack2(l2,l3);
        reinterpret_cast<uint2*>(&g_act[t][0][0])[i] = uh;
        reinterpret_cast<uint2*>(&g_act[t][1][0])[i] = ul;
    }
}

// ================= MMA stage =================
// CTA: M=128 rows x N=256 cols, one expert e = blockIdx.y; 512 thr = 16 warps (warp 32x64).
// Per phase (64-k chunk of one operand-matrix pair): smem gets Xhi,Xlo (16KB ea) + Whi,Wlo (32KB ea) = 96KB,
// double buffered (192KB). All 3 split products (AhWh + AhWl + AlWh) computed per phase into one acc.
// MODE: 0 LIN (A@L_e + B@R_e), 1 OMZ (A@R_e), 2 MUL ((A@L_e)*(B@R_e) via stash), 3 Z1R (LIN + sigmoid epi)
#define BUFSZ 98304

template<int MODE>
__global__ void __launch_bounds__(512, 1)
mma_stage(const __nv_bfloat16* __restrict__ aHi, const __nv_bfloat16* __restrict__ aLo,
          const __nv_bfloat16* __restrict__ bHi, const __nv_bfloat16* __restrict__ bLo,
          const float* __restrict__ bvec, float* __restrict__ gnode)
{
    extern __shared__ char smem[];
    const uint32_t sb = smem_u32(smem);
    const int tid = threadIdx.x, lane = tid & 31, warp = tid >> 5;
    const int wm = warp >> 2, wn = warp & 3;
    const int mtile = blockIdx.x, e = blockIdx.y;
    const int NP = ((MODE == 1) ? 1 : 2) * 4;

    float acc[2][8][4];
    #pragma unroll
    for (int i = 0; i < 2; i++)
    #pragma unroll
    for (int j = 0; j < 8; j++)
    #pragma unroll
    for (int q = 0; q < 4; q++) acc[i][j][q] = 0.0f;

    auto load_phase = [&](int it, int buf) {
        const int op = it >> 2, ch = it & 3;
        const int mat = (MODE == 1) ? 1 : op;
        const __nv_bfloat16* xs0 = op ? bHi : aHi;
        const __nv_bfloat16* xs1 = op ? bLo : aLo;
        const uint32_t xbase = sb + buf*BUFSZ;
        #pragma unroll
        for (int q = 0; q < 4; q++) {
            int s = tid + q*512;
            int sp = s >> 10, j = s & 1023;
            int r = j >> 3, sg = j & 7;
            cpasync16(xbase + sp*16384 + swz(r, sg*16),
                      (sp ? xs1 : xs0) + (size_t)(mtile*128 + r)*HID + ch*64 + sg*8);
        }
        const uint32_t wbase = sb + buf*BUFSZ + 32768;
        #pragma unroll
        for (int q = 0; q < 8; q++) {
            int s = tid + q*512;
            int sp = s >> 11, j = s & 2047;
            int n = j >> 3, sg = j & 7;
            cpasync16(wbase + sp*32768 + swz(n, sg*16),
                      g_w + W_IDX(e, mat, sp, (n >> 6), ch) + (n & 63)*64 + sg*8);
        }
    };

    const int la = lane & 15;
    const int kh = (lane >> 4) * 16;
    const int rA = wm*32 + la;
    const int nB = wn*64 + la;

    load_phase(0, 0); CP_COMMIT();
    for (int it = 0; it < NP; it++) {
        if (it + 1 < NP) { load_phase(it + 1, (it + 1) & 1); CP_COMMIT(); CP_WAIT(1); }
        else             { CP_WAIT(0); }
        __syncthreads();
        const uint32_t XH = sb + (it & 1)*BUFSZ;
        const uint32_t XL = XH + 16384;
        const uint32_t WH = XH + 32768;
        const uint32_t WL = XH + 65536;
        #pragma unroll
        for (int ks = 0; ks < 4; ks++) {
            const int cB = ks*32 + kh;
            uint32_t Ah[2][4], Al[2][4];
            ldsm4(Ah[0], XH + swz(rA,      cB));
            ldsm4(Ah[1], XH + swz(rA + 16, cB));
            ldsm4(Al[0], XL + swz(rA,      cB));
            ldsm4(Al[1], XL + swz(rA + 16, cB));
            #pragma unroll
            for (int pp = 0; pp < 4; pp++) {
                uint32_t BH[4], BL[4];
                ldsm4(BH, WH + swz(nB + pp*16, cB));
                ldsm4(BL, WL + swz(nB + pp*16, cB));
                const int f0 = pp*2;
                #pragma unroll
                for (int fm = 0; fm < 2; fm++) {
                    mma16816(acc[fm][f0],   Ah[fm], BH[0], BH[2]);
                    mma16816(acc[fm][f0+1], Ah[fm], BH[1], BH[3]);
                    mma16816(acc[fm][f0],   Ah[fm], BL[0], BL[2]);
                    mma16816(acc[fm][f0+1], Ah[fm], BL[1], BL[3]);
                    mma16816(acc[fm][f0],   Al[fm], BH[0], BH[2]);
                    mma16816(acc[fm][f0+1], Al[fm], BH[1], BH[3]);
                }
            }
        }
        __syncthreads();
        if (MODE == 2 && it == 3) {
            // stash first product (A@L_e) to g_cand, reset acc
            const int r0 = mtile*128 + wm*32 + (lane >> 2);
            const int c0 = wn*64 + (lane & 3)*2;
            #pragma unroll
            for (int fm = 0; fm < 2; fm++)
            #pragma unroll
            for (int fn = 0; fn < 8; fn++)
            #pragma unroll
            for (int h2 = 0; h2 < 2; h2++) {
                const int row = r0 + fm*16 + h2*8;
                const int col = c0 + fn*8;
                float2 st; st.x = acc[fm][fn][h2*2]; st.y = acc[fm][fn][h2*2+1];
                *reinterpret_cast<float2*>(&g_cand[((size_t)row*3 + e)*HID + col]) = st;
                acc[fm][fn][h2*2] = 0.0f; acc[fm][fn][h2*2+1] = 0.0f;
            }
        }
    }

    // ---- epilogue ----
    const int r0 = mtile*128 + wm*32 + (lane >> 2);
    const int c0 = wn*64 + (lane & 3)*2;
    if (MODE == 3) {
        #pragma unroll
        for (int fm = 0; fm < 2; fm++)
        #pragma unroll
        for (int fn = 0; fn < 8; fn++)
        #pragma unroll
        for (int h2 = 0; h2 < 2; h2++) {
            const int row = r0 + fm*16 + h2*8;
            const int col = c0 + fn*8;
            #pragma unroll
            for (int j = 0; j < 2; j++) {
                float v = acc[fm][fn][h2*2 + j] + bvec[e*HID + col + j];
                float z = 1.0f / (1.0f + expf(-v));
                gnode[(size_t)row*GN_STRIDE + e*HID + col + j] = z;
                if (e == 0) gnode[(size_t)row*GN_STRIDE + 2*HID + col + j] = z;
                __nv_bfloat16 hi, lo; split_bf(z, hi, lo);
                g_act[2 + e][0][(size_t)row*HID + col + j] = hi;
                g_act[2 + e][1][(size_t)row*HID + col + j] = lo;
            }
        }
    } else {
        #pragma unroll
        for (int fm = 0; fm < 2; fm++)
        #pragma unroll
        for (int fn = 0; fn < 8; fn++)
        #pragma unroll
        for (int h2 = 0; h2 < 2; h2++) {
            const int row = r0 + fm*16 + h2*8;
            const int col = c0 + fn*8;
            float v0 = acc[fm][fn][h2*2], v1 = acc[fm][fn][h2*2+1];
            float* cp = &g_cand[((size_t)row*3 + e)*HID + col];
            if (MODE == 2) {
                float2 t = *reinterpret_cast<const float2*>(cp);
                v0 *= t.x; v1 *= t.y;
            }
            float2 st; st.x = v0; st.y = v1;
            *reinterpret_cast<float2*>(cp) = st;
        }
    }
}

// per-row mixture: bias + k=3 candidate (identity weights) + softmax combine + outputs + next-stage splits
template<int MODE>
__global__ void __launch_bounds__(256)
mixture_kernel(const float* __restrict__ A, long sA,
               const float* __restrict__ Bv, long sB,
               const float* __restrict__ bvec, const float* __restrict__ Ws,
               float* __restrict__ outSlot, float* __restrict__ out2,
               __nv_bfloat16* __restrict__ actHi, __nv_bfloat16* __restrict__ actLo,
               float* __restrict__ s_acc)
{
    __shared__ float ss[4];
    const int tid = threadIdx.x, rl = tid >> 5, lane = tid & 31;
    const long row = (long)blockIdx.x*8 + rl;
    const int c0 = lane*8;
    if (tid < 4) ss[tid] = 0.0f;
    __syncthreads();

    float cf[4][8], w8[8];
    #pragma unroll
    for (int j = 0; j < 8; j++) w8[j] = Ws[c0 + j];

    #pragma unroll
    for (int k = 0; k < 3; k++) {
        const float* cp = g_cand + ((size_t)row*3 + k)*HID + c0;
        float4 v0 = reinterpret_cast<const float4*>(cp)[0];
        float4 v1 = reinterpret_cast<const float4*>(cp)[1];
        float vv[8] = {v0.x, v0.y, v0.z, v0.w, v1.x, v1.y, v1.z, v1.w};
        #pragma unroll
        for (int j = 0; j < 8; j++) {
            float t = vv[j] + bvec[k*HID + c0 + j];
            cf[k][j] = (MODE == 1) ? (1.0f - t) : t;
        }
    }
    #pragma unroll
    for (int j = 0; j < 8; j++) {
        float a  = A[row*sA + c0 + j];
        float b3 = bvec[3*HID + c0 + j];
        if (MODE == 0)      cf[3][j] = a + Bv[row*sB + c0 + j] + b3;
        else if (MODE == 1) cf[3][j] = 1.0f - (a + b3);
        else                cf[3][j] = a * Bv[row*sB + c0 + j] + b3;
    }
    float d[4];
    #pragma unroll
    for (int k = 0; k < 4; k++) {
        float t = 0.f;
        #pragma unroll
        for (int j = 0; j < 8; j++) t = fmaf(cf[k][j], w8[j], t);
        #pragma unroll
        for (int off = 16; off; off >>= 1) t += __shfl_xor_sync(0xffffffffu, t, off);
        d[k] = t;
    }
    if (lane == 0) {
        atomicAdd(&ss[0], d[0]); atomicAdd(&ss[1], d[1]);
        atomicAdd(&ss[2], d[2]); atomicAdd(&ss[3], d[3]);
    }
    float mx = fmaxf(fmaxf(d[0], d[1]), fmaxf(d[2], d[3]));
    float e0 = expf(d[0]-mx), e1 = expf(d[1]-mx), e2 = expf(d[2]-mx), e3 = expf(d[3]-mx);
    float inv = 1.0f / (e0 + e1 + e2 + e3);
    float w0 = e0*inv, w1 = e1*inv, w2 = e2*inv, w3 = e3*inv;

    float o[8];
    #pragma unroll
    for (int j = 0; j < 8; j++)
        o[j] = w0*cf[0][j] + w1*cf[1][j] + w2*cf[2][j] + w3*cf[3][j];

    float* os = outSlot + row*GN_STRIDE + c0;
    #pragma unroll
    for (int j = 0; j < 8; j++) os[j] = o[j];
    if (out2) {
        float4 u0 = make_float4(o[0], o[1], o[2], o[3]);
        float4 u1 = make_float4(o[4], o[5], o[6], o[7]);
        reinterpret_cast<float4*>(out2 + row*HID + c0)[0] = u0;
        reinterpret_cast<float4*>(out2 + row*HID + c0)[1] = u1;
    }
    if (actHi) {
        __nv_bfloat16 hi[8], lo[8];
        #pragma unroll
        for (int j = 0; j < 8; j++) split_bf(o[j], hi[j], lo[j]);
        uint4 uh, ul;
        uh.x = pack2(hi[0],hi[1]); uh.y = pack2(hi[2],hi[3]); uh.z = pack2(hi[4],hi[5]); uh.w = pack2(hi[6],hi[7]);
        ul.x = pack2(lo[0],lo[1]); ul.y = pack2(lo[2],lo[3]); ul.z = pack2(lo[4],lo[5]); ul.w = pack2(lo[6],lo[7]);
        *reinterpret_cast<uint4*>(actHi + row*HID + c0) = uh;
        *reinterpret_cast<uint4*>(actLo + row*HID + c0) = ul;
    }
    __syncthreads();
    if (tid < 4) atomicAdd(&s_acc[tid], ss[tid]);
}

__global__ void finalize_kernel(float* __restrict__ out) {
    if (threadIdx.x == 0 && blockIdx.x == 0) {
        float* gstr = out + OFF_GSTR;
        float* mg   = out + OFF_MARG;
        gstr[0] = 0.0f; gstr[1] = 1.0f; gstr[2] = 0.0f;
        for (int st = 0; st < 6; st++) {
            float s[4] = {g_s[st*4+0], g_s[st*4+1], g_s[st*4+2], g_s[st*4+3]};
            int idx = 0; float best = s[0];
            #pragma unroll
            for (int i = 1; i < 4; i++) if (s[i] > best) { best = s[i]; idx = i; }
            float second = -INFINITY;
            #pragma unroll
            for (int i = 0; i < 4; i++) if (i != idx) second = fmaxf(second, s[i]);
            gstr[3 + st] = (float)idx;
            mg[st] = best - second;
        }
    }
}

extern "C" void kernel_launch(void* const* d_in, const int* in_sizes, int n_in,
                              void* d_out, int out_size)
{
    const float* x  = (const float*)d_in[0];
    const float* h  = (const float*)d_in[1];
    const float* L  = (const float*)d_in[2];
    const float* R  = (const float*)d_in[3];
    const float* b  = (const float*)d_in[4];
    const float* Ws = (const float*)d_in[5];
    float* out = (float*)d_out;
    float* gnode = out + OFF_GNODE;

    const int SMEM = 2*BUFSZ;   // 192KB
    cudaFuncSetAttribute((const void*)mma_stage<0>, cudaFuncAttributeMaxDynamicSharedMemorySize, SMEM);
    cudaFuncSetAttribute((const void*)mma_stage<1>, cudaFuncAttributeMaxDynamicSharedMemorySize, SMEM);
    cudaFuncSetAttribute((const void*)mma_stage<2>, cudaFuncAttributeMaxDynamicSharedMemorySize, SMEM);
    cudaFuncSetAttribute((const void*)mma_stage<3>, cudaFuncAttributeMaxDynamicSharedMemorySize, SMEM);

    float* s_dev = nullptr;
    cudaGetSymbolAddress((void**)&s_dev, g_s);
    __nv_bfloat16* actB = nullptr;
    cudaGetSymbolAddress((void**)&actB, g_act);
    auto act = [&](int t, int sp) { return actB + ((size_t)t*2 + sp)*((size_t)BATCH*HID); };

    zero_s_kernel<<<1, 32>>>();
    wprep_kernel<<<96, 256>>>(L, R);
    xconv_kernel<<<(BATCH*HID/4 + 255)/256, 256>>>(x, h);

    const dim3 G3(128, 3), G2(128, 2);
    const int GM = BATCH/8;   // 2048

    // z1 (slots 0,2) + r (slot 1), sigmoid epilogue, splits -> act2 (z1), act3 (r)
    mma_stage<3><<<G2, 512, SMEM>>>(act(0,0), act(0,1), act(1,0), act(1,1), b, gnode);

    // s1: rh = mix(h@L + r@R + b) -> slot3, act4
    mma_stage<0><<<G3, 512, SMEM>>>(act(1,0), act(1,1), act(3,0), act(3,1), nullptr, nullptr);
    mixture_kernel<0><<<GM, 256>>>(h, (long)HID, gnode + 1*HID, (long)GN_STRIDE, b, Ws,
                                   gnode + 3*HID, nullptr, act(4,0), act(4,1), s_dev + 0);
    // s2: h_tilde = mix(x@L + rh@R + b) -> slot4, act5
    mma_stage<0><<<G3, 512, SMEM>>>(act(0,0), act(0,1), act(4,0), act(4,1), nullptr, nullptr);
    mixture_kernel<0><<<GM, 256>>>(x, (long)HID, gnode + 3*HID, (long)GN_STRIDE, b, Ws,
                                   gnode + 4*HID, nullptr, act(5,0), act(5,1), s_dev + 4);
    // s3: omz = mix(1 - (z1@R + b)) -> slot5, act6
    mma_stage<1><<<G3, 512, SMEM>>>(act(2,0), act(2,1), nullptr, nullptr, nullptr, nullptr);
    mixture_kernel<1><<<GM, 256>>>(gnode + 0*HID, (long)GN_STRIDE, nullptr, 0, b, Ws,
                                   gnode + 5*HID, nullptr, act(6,0), act(6,1), s_dev + 8);
    // s4: zh_tilde = mix((h_tilde@L)*(omz@R) + b) -> slot6, act7
    mma_stage<2><<<G3, 512, SMEM>>>(act(5,0), act(5,1), act(6,0), act(6,1), nullptr, nullptr);
    mixture_kernel<2><<<GM, 256>>>(gnode + 4*HID, (long)GN_STRIDE, gnode + 5*HID, (long)GN_STRIDE, b, Ws,
                                   gnode + 6*HID, nullptr, act(7,0), act(7,1), s_dev + 12);
    // s5: z2h = mix((h@L)*(z1@R) + b) -> slot7, act8
    mma_stage<2><<<G3, 512, SMEM>>>(act(1,0), act(1,1), act(2,0), act(2,1), nullptr, nullptr);
    mixture_kernel<2><<<GM, 256>>>(h, (long)HID, gnode + 0*HID, (long)GN_STRIDE, b, Ws,
                                   gnode + 7*HID, nullptr, act(8,0), act(8,1), s_dev + 16);
    // s6: h_next = mix(zh@L + z2h@R + b) -> slot8 + h_next output
    mma_stage<0><<<G3, 512, SMEM>>>(act(7,0), act(7,1), act(8,0), act(8,1), nullptr, nullptr);
    mixture_kernel<0><<<GM, 256>>>(gnode + 6*HID, (long)GN_STRIDE, gnode + 7*HID, (long)GN_STRIDE, b, Ws,
                                   gnode + 8*HID, out + OFF_HNEXT, nullptr, nullptr, s_dev + 20);

    finalize_kernel<<<1, 32>>>(out);
}

// round 8
// speedup vs baseline: 1.0744x; 1.0744x over previous
#include <cuda_runtime.h>
#include <cuda_bf16.h>
#include <stdint.h>
#include <math.h>

#define HID   256
#define BATCH 16384

// ---- output layout (floats) ----
#define OFF_HNEXT 0
#define OFF_GSTR  (BATCH*HID)
#define OFF_GNODE (OFF_GSTR + 9)
#define OFF_MARG  (OFF_GNODE + (long)BATCH*9*HID)
#define GN_STRIDE (9*HID)

// ---- static device scratch ----
// activations (bf16 hi/lo splits, row-major [BATCH][HID]):
// 0:x 1:h 2:z1 3:r 4:rh 5:h_tilde 6:omz 7:zh_tilde 8:z2h
__device__ __align__(16) __nv_bfloat16 g_act[9][2][(size_t)BATCH*HID];
// weight tiles [n(64)][kk(64)] bf16 (i.e. W^T): [e][mat][sp][nt64][ch64]
__device__ __align__(16) __nv_bfloat16 g_w[3*2*2*4*4*4096];
#define W_IDX(k,mat,sp,nt,ch) ((((((size_t)(k)*2+(mat))*2+(sp))*4+(nt))*4+(ch))*4096)
// candidates (pre-bias) [row][e 0..2][256] fp32 (also MUL-stage stash)
__device__ __align__(16) float g_cand[(size_t)BATCH*3*HID];
__device__ float g_s[24];

// ---- helpers ----
__device__ __forceinline__ uint32_t smem_u32(const void* p) {
    uint32_t a;
    asm("{ .reg .u64 t; cvta.to.shared.u64 t, %1; cvt.u32.u64 %0, t; }" : "=r"(a) : "l"(p));
    return a;
}
__device__ __forceinline__ void cpasync16(uint32_t dst, const void* src) {
    asm volatile("cp.async.cg.shared.global [%0], [%1], 16;" :: "r"(dst), "l"(src));
}
#define CP_COMMIT() asm volatile("cp.async.commit_group;" ::: "memory")
#define CP_WAIT(n)  asm volatile("cp.async.wait_group %0;" :: "n"(n) : "memory")

__device__ __forceinline__ void ldsm4(uint32_t* r, uint32_t addr) {
    asm volatile("ldmatrix.sync.aligned.m8n8.x4.shared.b16 {%0,%1,%2,%3}, [%4];"
        : "=r"(r[0]), "=r"(r[1]), "=r"(r[2]), "=r"(r[3]) : "r"(addr));
}
__device__ __forceinline__ void mma16816(float* c, const uint32_t* a, uint32_t b0, uint32_t b1) {
    asm volatile("mma.sync.aligned.m16n8k16.row.col.f32.bf16.bf16.f32 "
        "{%0,%1,%2,%3}, {%4,%5,%6,%7}, {%8,%9}, {%0,%1,%2,%3};"
        : "+f"(c[0]), "+f"(c[1]), "+f"(c[2]), "+f"(c[3])
        : "r"(a[0]), "r"(a[1]), "r"(a[2]), "r"(a[3]), "r"(b0), "r"(b1));
}
__device__ __forceinline__ void split_bf(float v, __nv_bfloat16& hi, __nv_bfloat16& lo) {
    hi = __float2bfloat16(v);
    lo = __float2bfloat16(v - __bfloat162float(hi));
}
__device__ __forceinline__ uint32_t pack2(__nv_bfloat16 a, __nv_bfloat16 b) {
    __nv_bfloat162 t; t.x = a; t.y = b;
    return *reinterpret_cast<uint32_t*>(&t);
}
// swizzled byte offset for 64B-row tiles (K32 chunks)
__device__ __forceinline__ int swz64(int off) { return off ^ ((off >> 3) & 0x30); }

__global__ void zero_s_kernel() { if (threadIdx.x < 24) g_s[threadIdx.x] = 0.0f; }

// split + transpose weights into [n][kk] tiles
__global__ void __launch_bounds__(256) wprep_kernel(const float* __restrict__ L, const float* __restrict__ R) {
    int b = blockIdx.x;
    int ch = b & 3, nt = (b >> 2) & 3, mat = (b >> 4) & 1, k = b >> 5;
    const float* W = (mat ? R : L) + (size_t)k*HID*HID;
    __nv_bfloat16* th = g_w + W_IDX(k, mat, 0, nt, ch);
    __nv_bfloat16* tl = g_w + W_IDX(k, mat, 1, nt, ch);
    for (int e = threadIdx.x; e < 4096; e += 256) {
        int n = e >> 6, kk = e & 63;
        float w = W[(size_t)(ch*64 + kk)*HID + nt*64 + n];
        __nv_bfloat16 hi, lo; split_bf(w, hi, lo);
        th[n*64 + kk] = hi; tl[n*64 + kk] = lo;
    }
}

// split x,h into g_act[0], g_act[1]
__global__ void __launch_bounds__(256) xconv_kernel(const float* __restrict__ x, const float* __restrict__ h) {
    size_t i = (size_t)blockIdx.x*256 + threadIdx.x;
    if (i >= (size_t)BATCH*HID/4) return;
    #pragma unroll
    for (int t = 0; t < 2; t++) {
        const float4 v = reinterpret_cast<const float4*>(t ? h : x)[i];
        __nv_bfloat16 h0,h1,h2,h3,l0,l1,l2,l3;
        split_bf(v.x,h0,l0); split_bf(v.y,h1,l1); split_bf(v.z,h2,l2); split_bf(v.w,h3,l3);
        uint2 uh; uh.x = pack2(h0,h1); uh.y = pack2(h2,h3);
        uint2 ul; ul.x = pack2(l0,l1); ul.y = pack2(l2,l3);
        reinterpret_cast<uint2*>(&g_act[t][0][0])[i] = uh;
        reinterpret_cast<uint2*>(&g_act[t][1][0])[i] = ul;
    }
}

// ================= MMA stage =================
// CTA 128M x 128N (nt = blockIdx.y), expert e = blockIdx.z. 256 thr = 8 warps (warp 32x64).
// K32 phases: per phase smem buffer 32KB = Xhi(8K)+Xlo(8K)+Whi(8K)+Wlo(8K), rows 64B, swz64.
// 3-stage cp.async pipeline (3 x 32KB = 96KB smem/CTA, 2 CTAs/SM).
// MODE: 0 LIN (A@L_e + B@R_e), 1 OMZ (A@R_e), 2 MUL ((A@L_e)*(B@R_e) via stash), 3 Z1R (LIN + sigmoid epi)
#define PHSZ 32768

template<int MODE>
__global__ void __launch_bounds__(256, 2)
mma_stage(const __nv_bfloat16* __restrict__ aHi, const __nv_bfloat16* __restrict__ aLo,
          const __nv_bfloat16* __restrict__ bHi, const __nv_bfloat16* __restrict__ bLo,
          const float* __restrict__ bvec, float* __restrict__ gnode)
{
    extern __shared__ char smem[];
    const uint32_t sb = smem_u32(smem);
    const int tid = threadIdx.x, lane = tid & 31, warp = tid >> 5;
    const int wm = warp >> 1, wn = warp & 1;
    const int mtile = blockIdx.x, nt = blockIdx.y, e = blockIdx.z;
    const int NPH = (MODE == 1) ? 8 : 16;

    float acc[2][8][4];
    #pragma unroll
    for (int i = 0; i < 2; i++)
    #pragma unroll
    for (int j = 0; j < 8; j++)
    #pragma unroll
    for (int q = 0; q < 4; q++) acc[i][j][q] = 0.0f;

    auto load_phase = [&](int it, int buf) {
        const int op = it >> 3, ch = it & 7;
        const int mat = (MODE == 1) ? 1 : op;
        const __nv_bfloat16* x0 = op ? bHi : aHi;
        const __nv_bfloat16* x1 = op ? bLo : aLo;
        const uint32_t base = sb + buf*PHSZ;
        #pragma unroll
        for (int q = 0; q < 4; q++) {             // X: 1024 x 16B
            int s = tid + q*256;
            int sp = s >> 9, j = s & 511;
            int r = j >> 2, sg = j & 3;
            cpasync16(base + sp*8192 + swz64(r*64 + sg*16),
                      (sp ? x1 : x0) + (size_t)(mtile*128 + r)*HID + ch*32 + sg*8);
        }
        #pragma unroll
        for (int q = 0; q < 4; q++) {             // W: 1024 x 16B
            int s = tid + q*256;
            int sp = s >> 9, j = s & 511;
            int n = j >> 2, sg = j & 3;
            cpasync16(base + 16384 + sp*8192 + swz64(n*64 + sg*16),
                      g_w + W_IDX(e, mat, sp, nt*2 + (n >> 6), ch >> 1)
                          + (n & 63)*64 + (ch & 1)*32 + sg*8);
        }
    };

    const int la = lane & 15;
    const int kh = (lane >> 4) * 16;   // byte offset of k-half for ldmatrix
    const int rA = wm*32 + la;
    const int nB = wn*64 + la;

    load_phase(0, 0); CP_COMMIT();
    load_phase(1, 1); CP_COMMIT();

    for (int it = 0; it < NPH; it++) {
        if (it + 1 < NPH) { CP_WAIT(1); } else { CP_WAIT(0); }
        __syncthreads();
        const uint32_t XH = sb + (it % 3)*PHSZ;
        const uint32_t XL = XH + 8192;
        const uint32_t WH = XH + 16384;
        const uint32_t WL = XH + 24576;
        #pragma unroll
        for (int ks = 0; ks < 2; ks++) {
            const int cB = ks*32 + kh;
            uint32_t Ah[2][4], Al[2][4];
            ldsm4(Ah[0], XH + swz64( rA      *64 + cB));
            ldsm4(Ah[1], XH + swz64((rA + 16)*64 + cB));
            ldsm4(Al[0], XL + swz64( rA      *64 + cB));
            ldsm4(Al[1], XL + swz64((rA + 16)*64 + cB));
            #pragma unroll
            for (int pph = 0; pph < 2; pph++) {
                uint32_t BH[2][4], BL[2][4];
                ldsm4(BH[0], WH + swz64((nB + pph*32     )*64 + cB));
                ldsm4(BH[1], WH + swz64((nB + pph*32 + 16)*64 + cB));
                ldsm4(BL[0], WL + swz64((nB + pph*32     )*64 + cB));
                ldsm4(BL[1], WL + swz64((nB + pph*32 + 16)*64 + cB));
                const int f0 = pph*4;
                // product-major: 8 independent accs between same-acc reuses
                #pragma unroll
                for (int fm = 0; fm < 2; fm++)
                #pragma unroll
                for (int pq = 0; pq < 2; pq++) {
                    mma16816(acc[fm][f0+pq*2],   Ah[fm], BH[pq][0], BH[pq][2]);
                    mma16816(acc[fm][f0+pq*2+1], Ah[fm], BH[pq][1], BH[pq][3]);
                }
                #pragma unroll
                for (int fm = 0; fm < 2; fm++)
                #pragma unroll
                for (int pq = 0; pq < 2; pq++) {
                    mma16816(acc[fm][f0+pq*2],   Ah[fm], BL[pq][0], BL[pq][2]);
                    mma16816(acc[fm][f0+pq*2+1], Ah[fm], BL[pq][1], BL[pq][3]);
                }
                #pragma unroll
                for (int fm = 0; fm < 2; fm++)
                #pragma unroll
                for (int pq = 0; pq < 2; pq++) {
                    mma16816(acc[fm][f0+pq*2],   Al[fm], BH[pq][0], BH[pq][2]);
                    mma16816(acc[fm][f0+pq*2+1], Al[fm], BH[pq][1], BH[pq][3]);
                }
            }
        }
        if (MODE == 2 && it == 7) {
            // stash first product (A@L_e) to g_cand, reset acc
            const int r0s = mtile*128 + wm*32 + (lane >> 2);
            const int c0s = nt*128 + wn*64 + (lane & 3)*2;
            #pragma unroll
            for (int fm = 0; fm < 2; fm++)
            #pragma unroll
            for (int fn = 0; fn < 8; fn++)
            #pragma unroll
            for (int h2 = 0; h2 < 2; h2++) {
                const int row = r0s + fm*16 + h2*8;
                const int col = c0s + fn*8;
                float2 st; st.x = acc[fm][fn][h2*2]; st.y = acc[fm][fn][h2*2+1];
                *reinterpret_cast<float2*>(&g_cand[((size_t)row*3 + e)*HID + col]) = st;
                acc[fm][fn][h2*2] = 0.0f; acc[fm][fn][h2*2+1] = 0.0f;
            }
        }
        if (it + 2 < NPH) { load_phase(it + 2, (it + 2) % 3); CP_COMMIT(); }
    }

    // ---- epilogue ----
    const int r0 = mtile*128 + wm*32 + (lane >> 2);
    const int c0 = nt*128 + wn*64 + (lane & 3)*2;
    if (MODE == 3) {
        #pragma unroll
        for (int fm = 0; fm < 2; fm++)
        #pragma unroll
        for (int fn = 0; fn < 8; fn++)
        #pragma unroll
        for (int h2 = 0; h2 < 2; h2++) {
            const int row = r0 + fm*16 + h2*8;
            const int col = c0 + fn*8;
            #pragma unroll
            for (int j = 0; j < 2; j++) {
                float v = acc[fm][fn][h2*2 + j] + bvec[e*HID + col + j];
                float z = 1.0f / (1.0f + expf(-v));
                gnode[(size_t)row*GN_STRIDE + e*HID + col + j] = z;
                if (e == 0) gnode[(size_t)row*GN_STRIDE + 2*HID + col + j] = z;
                __nv_bfloat16 hi, lo; split_bf(z, hi, lo);
                g_act[2 + e][0][(size_t)row*HID + col + j] = hi;
                g_act[2 + e][1][(size_t)row*HID + col + j] = lo;
            }
        }
    } else {
        #pragma unroll
        for (int fm = 0; fm < 2; fm++)
        #pragma unroll
        for (int fn = 0; fn < 8; fn++)
        #pragma unroll
        for (int h2 = 0; h2 < 2; h2++) {
            const int row = r0 + fm*16 + h2*8;
            const int col = c0 + fn*8;
            float v0 = acc[fm][fn][h2*2], v1 = acc[fm][fn][h2*2+1];
            float* cp = &g_cand[((size_t)row*3 + e)*HID + col];
            if (MODE == 2) {
                float2 t = *reinterpret_cast<const float2*>(cp);
                v0 *= t.x; v1 *= t.y;
            }
            float2 st; st.x = v0; st.y = v1;
            *reinterpret_cast<float2*>(cp) = st;
        }
    }
}

// per-row mixture: bias + k=3 candidate (identity weights) + softmax combine + outputs + next-stage splits
template<int MODE>
__global__ void __launch_bounds__(256)
mixture_kernel(const float* __restrict__ A, long sA,
               const float* __restrict__ Bv, long sB,
               const float* __restrict__ bvec, const float* __restrict__ Ws,
               float* __restrict__ outSlot, float* __restrict__ out2,
               __nv_bfloat16* __restrict__ actHi, __nv_bfloat16* __restrict__ actLo,
               float* __restrict__ s_acc)
{
    __shared__ float ss[4];
    const int tid = threadIdx.x, rl = tid >> 5, lane = tid & 31;
    const long row = (long)blockIdx.x*8 + rl;
    const int c0 = lane*8;
    if (tid < 4) ss[tid] = 0.0f;
    __syncthreads();

    float cf[4][8], w8[8];
    #pragma unroll
    for (int j = 0; j < 8; j++) w8[j] = Ws[c0 + j];

    #pragma unroll
    for (int k = 0; k < 3; k++) {
        const float* cp = g_cand + ((size_t)row*3 + k)*HID + c0;
        float4 v0 = reinterpret_cast<const float4*>(cp)[0];
        float4 v1 = reinterpret_cast<const float4*>(cp)[1];
        float vv[8] = {v0.x, v0.y, v0.z, v0.w, v1.x, v1.y, v1.z, v1.w};
        #pragma unroll
        for (int j = 0; j < 8; j++) {
            float t = vv[j] + bvec[k*HID + c0 + j];
            cf[k][j] = (MODE == 1) ? (1.0f - t) : t;
        }
    }
    #pragma unroll
    for (int j = 0; j < 8; j++) {
        float a  = A[row*sA + c0 + j];
        float b3 = bvec[3*HID + c0 + j];
        if (MODE == 0)      cf[3][j] = a + Bv[row*sB + c0 + j] + b3;
        else if (MODE == 1) cf[3][j] = 1.0f - (a + b3);
        else                cf[3][j] = a * Bv[row*sB + c0 + j] + b3;
    }
    float d[4];
    #pragma unroll
    for (int k = 0; k < 4; k++) {
        float t = 0.f;
        #pragma unroll
        for (int j = 0; j < 8; j++) t = fmaf(cf[k][j], w8[j], t);
        #pragma unroll
        for (int off = 16; off; off >>= 1) t += __shfl_xor_sync(0xffffffffu, t, off);
        d[k] = t;
    }
    if (lane == 0) {
        atomicAdd(&ss[0], d[0]); atomicAdd(&ss[1], d[1]);
        atomicAdd(&ss[2], d[2]); atomicAdd(&ss[3], d[3]);
    }
    float mx = fmaxf(fmaxf(d[0], d[1]), fmaxf(d[2], d[3]));
    float e0 = expf(d[0]-mx), e1 = expf(d[1]-mx), e2 = expf(d[2]-mx), e3 = expf(d[3]-mx);
    float inv = 1.0f / (e0 + e1 + e2 + e3);
    float w0 = e0*inv, w1 = e1*inv, w2 = e2*inv, w3 = e3*inv;

    float o[8];
    #pragma unroll
    for (int j = 0; j < 8; j++)
        o[j] = w0*cf[0][j] + w1*cf[1][j] + w2*cf[2][j] + w3*cf[3][j];

    float* os = outSlot + row*GN_STRIDE + c0;
    #pragma unroll
    for (int j = 0; j < 8; j++) os[j] = o[j];
    if (out2) {
        float4 u0 = make_float4(o[0], o[1], o[2], o[3]);
        float4 u1 = make_float4(o[4], o[5], o[6], o[7]);
        reinterpret_cast<float4*>(out2 + row*HID + c0)[0] = u0;
        reinterpret_cast<float4*>(out2 + row*HID + c0)[1] = u1;
    }
    if (actHi) {
        __nv_bfloat16 hi[8], lo[8];
        #pragma unroll
        for (int j = 0; j < 8; j++) split_bf(o[j], hi[j], lo[j]);
        uint4 uh, ul;
        uh.x = pack2(hi[0],hi[1]); uh.y = pack2(hi[2],hi[3]); uh.z = pack2(hi[4],hi[5]); uh.w = pack2(hi[6],hi[7]);
        ul.x = pack2(lo[0],lo[1]); ul.y = pack2(lo[2],lo[3]); ul.z = pack2(lo[4],lo[5]); ul.w = pack2(lo[6],lo[7]);
        *reinterpret_cast<uint4*>(actHi + row*HID + c0) = uh;
        *reinterpret_cast<uint4*>(actLo + row*HID + c0) = ul;
    }
    __syncthreads();
    if (tid < 4) atomicAdd(&s_acc[tid], ss[tid]);
}

__global__ void finalize_kernel(float* __restrict__ out) {
    if (threadIdx.x == 0 && blockIdx.x == 0) {
        float* gstr = out + OFF_GSTR;
        float* mg   = out + OFF_MARG;
        gstr[0] = 0.0f; gstr[1] = 1.0f; gstr[2] = 0.0f;
        for (int st = 0; st < 6; st++) {
            float s[4] = {g_s[st*4+0], g_s[st*4+1], g_s[st*4+2], g_s[st*4+3]};
            int idx = 0; float best = s[0];
            #pragma unroll
            for (int i = 1; i < 4; i++) if (s[i] > best) { best = s[i]; idx = i; }
            float second = -INFINITY;
            #pragma unroll
            for (int i = 0; i < 4; i++) if (i != idx) second = fmaxf(second, s[i]);
            gstr[3 + st] = (float)idx;
            mg[st] = best - second;
        }
    }
}

extern "C" void kernel_launch(void* const* d_in, const int* in_sizes, int n_in,
                              void* d_out, int out_size)
{
    const float* x  = (const float*)d_in[0];
    const float* h  = (const float*)d_in[1];
    const float* L  = (const float*)d_in[2];
    const float* R  = (const float*)d_in[3];
    const float* b  = (const float*)d_in[4];
    const float* Ws = (const float*)d_in[5];
    float* out = (float*)d_out;
    float* gnode = out + OFF_GNODE;

    const int SMEM = 3*PHSZ;   // 96KB per CTA
    cudaFuncSetAttribute((const void*)mma_stage<0>, cudaFuncAttributeMaxDynamicSharedMemorySize, SMEM);
    cudaFuncSetAttribute((const void*)mma_stage<1>, cudaFuncAttributeMaxDynamicSharedMemorySize, SMEM);
    cudaFuncSetAttribute((const void*)mma_stage<2>, cudaFuncAttributeMaxDynamicSharedMemorySize, SMEM);
    cudaFuncSetAttribute((const void*)mma_stage<3>, cudaFuncAttributeMaxDynamicSharedMemorySize, SMEM);

    float* s_dev = nullptr;
    cudaGetSymbolAddress((void**)&s_dev, g_s);
    __nv_bfloat16* actB = nullptr;
    cudaGetSymbolAddress((void**)&actB, g_act);
    auto act = [&](int t, int sp) { return actB + ((size_t)t*2 + sp)*((size_t)BATCH*HID); };

    zero_s_kernel<<<1, 32>>>();
    wprep_kernel<<<96, 256>>>(L, R);
    xconv_kernel<<<(BATCH*HID/4 + 255)/256, 256>>>(x, h);

    const dim3 G3(128, 2, 3), G2(128, 2, 2);
    const int GM = BATCH/8;   // 2048

    // z1 (slots 0,2) + r (slot 1), sigmoid epilogue, splits -> act2 (z1), act3 (r)
    mma_stage<3><<<G2, 256, SMEM>>>(act(0,0), act(0,1), act(1,0), act(1,1), b, gnode);

    // s1: rh = mix(h@L + r@R + b) -> slot3, act4
    mma_stage<0><<<G3, 256, SMEM>>>(act(1,0), act(1,1), act(3,0), act(3,1), nullptr, nullptr);
    mixture_kernel<0><<<GM, 256>>>(h, (long)HID, gnode + 1*HID, (long)GN_STRIDE, b, Ws,
                                   gnode + 3*HID, nullptr, act(4,0), act(4,1), s_dev + 0);
    // s2: h_tilde = mix(x@L + rh@R + b) -> slot4, act5
    mma_stage<0><<<G3, 256, SMEM>>>(act(0,0), act(0,1), act(4,0), act(4,1), nullptr, nullptr);
    mixture_kernel<0><<<GM, 256>>>(x, (long)HID, gnode + 3*HID, (long)GN_STRIDE, b, Ws,
                                   gnode + 4*HID, nullptr, act(5,0), act(5,1), s_dev + 4);
    // s3: omz = mix(1 - (z1@R + b)) -> slot5, act6
    mma_stage<1><<<G3, 256, SMEM>>>(act(2,0), act(2,1), nullptr, nullptr, nullptr, nullptr);
    mixture_kernel<1><<<GM, 256>>>(gnode + 0*HID, (long)GN_STRIDE, nullptr, 0, b, Ws,
                                   gnode + 5*HID, nullptr, act(6,0), act(6,1), s_dev + 8);
    // s4: zh_tilde = mix((h_tilde@L)*(omz@R) + b) -> slot6, act7
    mma_stage<2><<<G3, 256, SMEM>>>(act(5,0), act(5,1), act(6,0), act(6,1), nullptr, nullptr);
    mixture_kernel<2><<<GM, 256>>>(gnode + 4*HID, (long)GN_STRIDE, gnode + 5*HID, (long)GN_STRIDE, b, Ws,
                                   gnode + 6*HID, nullptr, act(7,0), act(7,1), s_dev + 12);
    // s5: z2h = mix((h@L)*(z1@R) + b) -> slot7, act8
    mma_stage<2><<<G3, 256, SMEM>>>(act(1,0), act(1,1), act(2,0), act(2,1), nullptr, nullptr);
    mixture_kernel<2><<<GM, 256>>>(h, (long)HID, gnode + 0*HID, (long)GN_STRIDE, b, Ws,
                                   gnode + 7*HID, nullptr, act(8,0), act(8,1), s_dev + 16);
    // s6: h_next = mix(zh@L + z2h@R + b) -> slot8 + h_next output
    mma_stage<0><<<G3, 256, SMEM>>>(act(7,0), act(7,1), act(8,0), act(8,1), nullptr, nullptr);
    mixture_kernel<0><<<GM, 256>>>(gnode + 6*HID, (long)GN_STRIDE, gnode + 7*HID, (long)GN_STRIDE, b, Ws,
                                   gnode + 8*HID, out + OFF_HNEXT, nullptr, nullptr, s_dev + 20);

    finalize_kernel<<<1, 32>>>(out);
}